// round 13
// baseline (speedup 1.0000x reference)
#include <cuda_runtime.h>
#include <cuda_bf16.h>
#include <math.h>
#include <stdint.h>

#define Bc 2
#define Sc 4096
#define DMc 768
#define Hc 12
#define HDc 64
#define BHc (Bc*Hc)

#define LOG2E 1.4426950408889634f

// Scratch (allocation-free rule: __device__ globals)
__device__ __nv_bfloat16 g_xh[(size_t)Bc*Sc*DMc];     // bf16 hidden
__device__ __nv_bfloat16 g_wh[4][(size_t)DMc*DMc];    // bf16 Wq,Wk,Wv,Wo
__device__ __nv_bfloat16 g_qh[(size_t)BHc*Sc*HDc];    // bf16 q (RoPE'd, * log2e/64)
__device__ __nv_bfloat16 g_kh[(size_t)BHc*Sc*HDc];    // bf16 k (RoPE'd)
__device__ __nv_bfloat16 g_vh[(size_t)BHc*Sc*HDc];    // bf16 v
__device__ __nv_bfloat16 g_attnh[(size_t)Bc*Sc*DMc];  // bf16 attn out
__device__ float g_y[(size_t)Bc*Sc*DMc];              // fp32 pre-LN

// ---------------------------------------------------------------------------
// fp32 -> bf16 converts: grid.y = 0 -> hidden, 1..4 -> Wq..Wo
// ---------------------------------------------------------------------------
__global__ __launch_bounds__(256) void f2b_all_kernel(const float* __restrict__ hidden,
                                                      const float* __restrict__ Wq,
                                                      const float* __restrict__ Wk,
                                                      const float* __restrict__ Wv,
                                                      const float* __restrict__ Wo) {
    int which = blockIdx.y;
    const float* src;
    __nv_bfloat16* dst;
    int n4;
    if (which == 0) { src = hidden; dst = g_xh; n4 = (Bc * Sc * DMc) / 4; }
    else {
        src = (which == 1) ? Wq : (which == 2) ? Wk : (which == 3) ? Wv : Wo;
        dst = g_wh[which - 1];
        n4 = (DMc * DMc) / 4;
    }
    int i = blockIdx.x * blockDim.x + threadIdx.x;
    if (i >= n4) return;
    float4 v = *(const float4*)(src + (size_t)i * 4);
    __nv_bfloat162 a = __floats2bfloat162_rn(v.x, v.y);
    __nv_bfloat162 b = __floats2bfloat162_rn(v.z, v.w);
    *(__nv_bfloat162*)(dst + (size_t)i * 4 + 0) = a;
    *(__nv_bfloat162*)(dst + (size_t)i * 4 + 2) = b;
}

// ---------------------------------------------------------------------------
// helpers
// ---------------------------------------------------------------------------
__device__ __forceinline__ uint32_t pack_bf16(float lo, float hi) {
    __nv_bfloat162 h = __floats2bfloat162_rn(lo, hi);
    return *reinterpret_cast<uint32_t*>(&h);
}
__device__ __forceinline__ void cpa16(uint32_t s, const void* g) {
    asm volatile("cp.async.cg.shared.global [%0], [%1], 16;" :: "r"(s), "l"(g));
}
#define CP_COMMIT() asm volatile("cp.async.commit_group;")
#define CP_WAIT0()  asm volatile("cp.async.wait_group 0;")

#define LDSM4(r0,r1,r2,r3,addr) \
    asm volatile("ldmatrix.sync.aligned.m8n8.x4.shared.b16 {%0,%1,%2,%3},[%4];" \
                 : "=r"(r0),"=r"(r1),"=r"(r2),"=r"(r3) : "r"(addr))
#define LDSM4T(r0,r1,r2,r3,addr) \
    asm volatile("ldmatrix.sync.aligned.m8n8.x4.trans.shared.b16 {%0,%1,%2,%3},[%4];" \
                 : "=r"(r0),"=r"(r1),"=r"(r2),"=r"(r3) : "r"(addr))
#define MMA16816(c, a, b0, b1) \
    asm volatile("mma.sync.aligned.m16n8k16.row.col.f32.bf16.bf16.f32 " \
                 "{%0,%1,%2,%3},{%4,%5,%6,%7},{%8,%9},{%0,%1,%2,%3};" \
                 : "+f"((c)[0]),"+f"((c)[1]),"+f"((c)[2]),"+f"((c)[3]) \
                 : "r"((a)[0]),"r"((a)[1]),"r"((a)[2]),"r"((a)[3]),"r"(b0),"r"(b1))

// packed bf16x2 exp2 on the MUFU pipe: 2 results per instruction
#define EX2_BF16X2(dst, src) \
    asm("ex2.approx.ftz.bf16x2 %0, %1;" : "=r"(dst) : "r"(src))

// bf16x2 -> two fp32 (pure bit shifts) accumulated into l
#define SUMPF(reg, l) do { \
    uint32_t p_ = (reg); \
    (l) += __uint_as_float(p_ << 16) + __uint_as_float(p_ & 0xFFFF0000u); \
} while (0)

// ---------------------------------------------------------------------------
// Tensor-core GEMM: 256 threads / 8 warps, tile 128M x 128N, K-chunks of 64,
// double-buffered cp.async. Warp layout: warpM = warp>>1 (32-row strip),
// warpN = warp&1 (64-col half). Per-warp body identical to the proven R8
// kernel (acc[2][8][4]). X cp.async traffic halves vs 64N tiles; occupancy
// 2 CTAs x 8 warps = 16 warps/SM.
// MODE 0 (grid.z = sel): 0 -> RoPE * log2e/64 -> g_qh ; 1 -> RoPE -> g_kh ;
//                        2 -> +bias -> g_vh.  [b,h,s,d] bf16.
// MODE 1: g_y = acc + resid  (X = g_attnh)
// ---------------------------------------------------------------------------
#define GSTR 72
#define GEMM_SMEM ((2*128*GSTR + 2*128*GSTR) * 2)   // 73728 bytes

template <int MODE>
__global__ __launch_bounds__(256, 2) void gemm_tc(const __nv_bfloat16* __restrict__ X,
                                                  const __nv_bfloat16* __restrict__ Wbase,
                                                  const float* __restrict__ bq,
                                                  const float* __restrict__ bk,
                                                  const float* __restrict__ bv,
                                                  const float* __restrict__ resid,
                                                  const float* __restrict__ cosp,
                                                  const float* __restrict__ sinp) {
    extern __shared__ __align__(16) char smem_raw[];
    __nv_bfloat16* Xs = (__nv_bfloat16*)smem_raw;        // 2 x 128 x GSTR
    __nv_bfloat16* Ws = Xs + 2 * 128 * GSTR;             // 2 x 128 x GSTR

    const int tid  = threadIdx.x;
    const int warp = tid >> 5;
    const int lane = tid & 31;
    const int warpM = warp >> 1;        // 0..3
    const int warpN = warp & 1;         // 0..1
    const int rowBase = blockIdx.y * 128;
    const int colBase = blockIdx.x * 128;
    const int sel = (MODE == 0) ? blockIdx.z : 3;

    const __nv_bfloat16* W = Wbase + (size_t)sel * DMc * DMc;
    const float* bias = (MODE == 0) ? ((sel == 0) ? bq : (sel == 1) ? bk : bv) : nullptr;

    const uint32_t xs_b = (uint32_t)__cvta_generic_to_shared(Xs);
    const uint32_t ws_b = (uint32_t)__cvta_generic_to_shared(Ws);

    auto prefetch = [&](int kb, int buf) {
#pragma unroll
        for (int u = 0; u < 4; u++) {                    // X: 1024 16B-chunks
            int i = u * 256 + tid;
            int r = i >> 3, c = i & 7;
            cpa16(xs_b + ((buf * 128 + r) * GSTR + c * 8) * 2,
                  X + (size_t)(rowBase + r) * DMc + kb + c * 8);
        }
#pragma unroll
        for (int u = 0; u < 4; u++) {                    // W: 1024 16B-chunks
            int i = u * 256 + tid;
            int r = i >> 3, c = i & 7;
            cpa16(ws_b + ((buf * 128 + r) * GSTR + c * 8) * 2,
                  W + (size_t)(colBase + r) * DMc + kb + c * 8);
        }
    };

    float acc[2][8][4];
#pragma unroll
    for (int mt = 0; mt < 2; mt++)
#pragma unroll
        for (int nt = 0; nt < 8; nt++)
#pragma unroll
            for (int i = 0; i < 4; i++) acc[mt][nt][i] = 0.f;

    const int q8 = lane >> 3;
    const int bRow = ((q8 >> 1) * 8) + (lane & 7);
    const int bCol = (q8 & 1) * 8;
    const int aRow = lane & 15;
    const int aCol = (lane >> 4) * 8;

    prefetch(0, 0);
    CP_COMMIT();

    const int NCHUNK = DMc / 64;   // 12
    for (int kc = 0; kc < NCHUNK; kc++) {
        CP_WAIT0();
        __syncthreads();
        if (kc + 1 < NCHUNK) {
            prefetch((kc + 1) * 64, (kc + 1) & 1);
            CP_COMMIT();
        }
        int buf = kc & 1;
#pragma unroll
        for (int ks = 0; ks < 4; ks++) {
            uint32_t af[2][4];
#pragma unroll
            for (int mt = 0; mt < 2; mt++) {
                uint32_t a = xs_b + ((buf * 128 + warpM * 32 + mt * 16 + aRow) * GSTR + ks * 16 + aCol) * 2;
                LDSM4(af[mt][0], af[mt][1], af[mt][2], af[mt][3], a);
            }
            uint32_t bf[16];
#pragma unroll
            for (int ntp = 0; ntp < 4; ntp++) {
                uint32_t a = ws_b + ((buf * 128 + warpN * 64 + ntp * 16 + bRow) * GSTR + ks * 16 + bCol) * 2;
                LDSM4(bf[4*ntp], bf[4*ntp+1], bf[4*ntp+2], bf[4*ntp+3], a);
            }
#pragma unroll
            for (int mt = 0; mt < 2; mt++)
#pragma unroll
                for (int ntp = 0; ntp < 4; ntp++) {
                    MMA16816(acc[mt][2*ntp],   af[mt], bf[4*ntp],   bf[4*ntp+1]);
                    MMA16816(acc[mt][2*ntp+1], af[mt], bf[4*ntp+2], bf[4*ntp+3]);
                }
        }
    }

    // ---- epilogue ----
    if (MODE == 1) {
#pragma unroll
        for (int mt = 0; mt < 2; mt++) {
            int r0 = rowBase + warpM * 32 + mt * 16 + (lane >> 2);
#pragma unroll
            for (int nt = 0; nt < 8; nt++) {
                int col = colBase + warpN * 64 + nt * 8 + 2 * (lane & 3);
                size_t o0 = (size_t)r0 * DMc + col;
                size_t o1 = (size_t)(r0 + 8) * DMc + col;
                float2 w0 = make_float2(acc[mt][nt][0] + resid[o0],
                                        acc[mt][nt][1] + resid[o0 + 1]);
                float2 w1 = make_float2(acc[mt][nt][2] + resid[o1],
                                        acc[mt][nt][3] + resid[o1 + 1]);
                *(float2*)(g_y + o0) = w0;
                *(float2*)(g_y + o1) = w1;
            }
        }
        return;
    }

    __nv_bfloat16* dst = (sel == 0) ? g_qh : (sel == 1) ? g_kh : g_vh;
    const int headCol = colBase + warpN * 64;   // this warp's head base column
    const int h_ = headCol >> 6;
    const float scale = (sel == 0) ? (LOG2E / (float)HDc) : 1.0f;

#pragma unroll
    for (int mt = 0; mt < 2; mt++) {
        int r0 = rowBase + warpM * 32 + mt * 16 + (lane >> 2);
        int r1 = r0 + 8;
        int b0_ = r0 >> 12, s0_ = r0 & (Sc - 1);
        int b1_ = r1 >> 12, s1_ = r1 & (Sc - 1);
        size_t base0 = (((size_t)(b0_ * Hc + h_)) * Sc + s0_) * HDc;
        size_t base1 = (((size_t)(b1_ * Hc + h_)) * Sc + s1_) * HDc;

        if (sel == 2) {
#pragma unroll
            for (int nt = 0; nt < 8; nt++) {
                int d = nt * 8 + 2 * (lane & 3);
                float b_lo = bias[headCol + d], b_hi = bias[headCol + d + 1];
                *(__nv_bfloat162*)(dst + base0 + d) =
                    __floats2bfloat162_rn(acc[mt][nt][0] + b_lo, acc[mt][nt][1] + b_hi);
                *(__nv_bfloat162*)(dst + base1 + d) =
                    __floats2bfloat162_rn(acc[mt][nt][2] + b_lo, acc[mt][nt][3] + b_hi);
            }
        } else {
            // RoPE: pair (d, d+32) lives in (nt, nt+4)
#pragma unroll
            for (int nt = 0; nt < 4; nt++) {
                int d = nt * 8 + 2 * (lane & 3);
                float bl = bias[headCol + d],      bh = bias[headCol + d + 1];
                float bL = bias[headCol + d + 32], bH = bias[headCol + d + 33];
                float2 c0 = *(const float2*)(cosp + (size_t)s0_ * HDc + d);
                float2 sn0 = *(const float2*)(sinp + (size_t)s0_ * HDc + d);
                float2 c1 = *(const float2*)(cosp + (size_t)s1_ * HDc + d);
                float2 sn1 = *(const float2*)(sinp + (size_t)s1_ * HDc + d);
                {
                    float xa0 = acc[mt][nt][0] + bl,  xa1 = acc[mt][nt][1] + bh;
                    float xb0 = acc[mt][nt+4][0] + bL, xb1 = acc[mt][nt+4][1] + bH;
                    float lo0 = (xa0 * c0.x - xb0 * sn0.x) * scale;
                    float lo1 = (xa1 * c0.y - xb1 * sn0.y) * scale;
                    float hi0 = (xb0 * c0.x + xa0 * sn0.x) * scale;
                    float hi1 = (xb1 * c0.y + xa1 * sn0.y) * scale;
                    *(__nv_bfloat162*)(dst + base0 + d)      = __floats2bfloat162_rn(lo0, lo1);
                    *(__nv_bfloat162*)(dst + base0 + d + 32) = __floats2bfloat162_rn(hi0, hi1);
                }
                {
                    float xa0 = acc[mt][nt][2] + bl,  xa1 = acc[mt][nt][3] + bh;
                    float xb0 = acc[mt][nt+4][2] + bL, xb1 = acc[mt][nt+4][3] + bH;
                    float lo0 = (xa0 * c1.x - xb0 * sn1.x) * scale;
                    float lo1 = (xa1 * c1.y - xb1 * sn1.y) * scale;
                    float hi0 = (xb0 * c1.x + xa0 * sn1.x) * scale;
                    float hi1 = (xb1 * c1.y + xa1 * sn1.y) * scale;
                    *(__nv_bfloat162*)(dst + base1 + d)      = __floats2bfloat162_rn(lo0, lo1);
                    *(__nv_bfloat162*)(dst + base1 + d + 32) = __floats2bfloat162_rn(hi0, hi1);
                }
            }
        }
    }
}

// ---------------------------------------------------------------------------
// Flash attention (R10 proven shape: 128 threads / 4 warps, 64 q rows,
// double-buffered K/V cp.async, static 46KB smem, unnormalized softmax,
// bf16x2 exp2). R12: row sums OFF the tensor pipe (bit-shift unpack + FADD
// on the idle FMA pipe) — removes the 4 ones-MMAs (6% of tensor work,
// the binding pipe).
// ---------------------------------------------------------------------------
#define SSTR 72

__global__ __launch_bounds__(128) void flash_mma_kernel() {
    __shared__ __align__(16) __nv_bfloat16 Qs[64 * SSTR];
    __shared__ __align__(16) __nv_bfloat16 Ks[2][64 * SSTR];
    __shared__ __align__(16) __nv_bfloat16 Vs[2][64 * SSTR];

    const int tid  = threadIdx.x;
    const int warp = tid >> 5;
    const int lane = tid & 31;
    const int bh   = blockIdx.y;
    const int q0   = blockIdx.x * 64;

    const __nv_bfloat16* qg = g_qh + ((size_t)bh * Sc + q0) * HDc;
    const __nv_bfloat16* kg = g_kh + (size_t)bh * Sc * HDc;
    const __nv_bfloat16* vg = g_vh + (size_t)bh * Sc * HDc;

    const uint32_t qs_b = (uint32_t)__cvta_generic_to_shared(Qs);
    const uint32_t ks0 = (uint32_t)__cvta_generic_to_shared(Ks[0]);
    const uint32_t vs0 = (uint32_t)__cvta_generic_to_shared(Vs[0]);
    const uint32_t kvstep = (uint32_t)(64 * SSTR * 2);

    auto prefkv = [&](int j0, int buf) {
        uint32_t kb = ks0 + buf * kvstep;
        uint32_t vb = vs0 + buf * kvstep;
#pragma unroll
        for (int u = 0; u < 4; u++) {
            int i = u * 128 + tid;
            int r = i >> 3, c = i & 7;
            cpa16(kb + (r * SSTR + c * 8) * 2, kg + (size_t)(j0 + r) * HDc + c * 8);
            cpa16(vb + (r * SSTR + c * 8) * 2, vg + (size_t)(j0 + r) * HDc + c * 8);
        }
    };

#pragma unroll
    for (int u = 0; u < 4; u++) {
        int i = u * 128 + tid;
        int r = i >> 3, c = i & 7;
        *(uint4*)&Qs[r * SSTR + c * 8] = *(const uint4*)(qg + (size_t)r * HDc + c * 8);
    }
    prefkv(0, 0);
    CP_COMMIT();
    __syncthreads();

    uint32_t qf[4][4];
    {
        int row = (lane & 15);
        int colo = (lane >= 16) ? 8 : 0;
#pragma unroll
        for (int ks = 0; ks < 4; ks++) {
            uint32_t a = qs_b + ((warp * 16 + row) * SSTR + ks * 16 + colo) * 2;
            LDSM4(qf[ks][0], qf[ks][1], qf[ks][2], qf[ks][3], a);
        }
    }

    const int q8 = lane >> 3;
    const int kRow = ((q8 >> 1) * 8) + (lane & 7);
    const int kCol = (q8 & 1) * 8;
    const int vRow = ((q8 & 1) * 8) + (lane & 7);
    const int vCol = (q8 >> 1) * 8;

    float o[8][4];
#pragma unroll
    for (int nt = 0; nt < 8; nt++)
#pragma unroll
        for (int i = 0; i < 4; i++) o[nt][i] = 0.f;
    float l0 = 0.f, l1 = 0.f;   // per-lane partial row sums

    const int NT = Sc / 64;   // 64 tiles
    for (int jt = 0; jt < NT; jt++) {
        CP_WAIT0();
        __syncthreads();
        if (jt + 1 < NT) {
            prefkv((jt + 1) * 64, (jt + 1) & 1);
            CP_COMMIT();
        }
        int buf = jt & 1;
        uint32_t ks_b = ks0 + buf * kvstep;
        uint32_t vs_b = vs0 + buf * kvstep;

        float s[8][4];
#pragma unroll
        for (int nt = 0; nt < 8; nt++)
#pragma unroll
            for (int i = 0; i < 4; i++) s[nt][i] = 0.f;

#pragma unroll
        for (int ks = 0; ks < 4; ks++) {
            uint32_t kf[16];
#pragma unroll
            for (int ntp = 0; ntp < 4; ntp++) {
                uint32_t a = ks_b + ((ntp * 16 + kRow) * SSTR + ks * 16 + kCol) * 2;
                LDSM4(kf[4*ntp], kf[4*ntp+1], kf[4*ntp+2], kf[4*ntp+3], a);
            }
#pragma unroll
            for (int ntp = 0; ntp < 4; ntp++) {
                MMA16816(s[2*ntp],   qf[ks], kf[4*ntp],   kf[4*ntp+1]);
                MMA16816(s[2*ntp+1], qf[ks], kf[4*ntp+2], kf[4*ntp+3]);
            }
        }

        // unnormalized softmax: pack scores to bf16x2, exp2 in bf16x2 (2-wide
        // MUFU). Row sums via bit-shift unpack + FADD (FMA pipe, not tensor).
        uint32_t pf[4][4];
#pragma unroll
        for (int ks2 = 0; ks2 < 4; ks2++) {
            uint32_t t0 = pack_bf16(s[2*ks2][0],   s[2*ks2][1]);
            uint32_t t1 = pack_bf16(s[2*ks2][2],   s[2*ks2][3]);
            uint32_t t2 = pack_bf16(s[2*ks2+1][0], s[2*ks2+1][1]);
            uint32_t t3 = pack_bf16(s[2*ks2+1][2], s[2*ks2+1][3]);
            EX2_BF16X2(pf[ks2][0], t0);
            EX2_BF16X2(pf[ks2][1], t1);
            EX2_BF16X2(pf[ks2][2], t2);
            EX2_BF16X2(pf[ks2][3], t3);
            SUMPF(pf[ks2][0], l0);
            SUMPF(pf[ks2][2], l0);
            SUMPF(pf[ks2][1], l1);
            SUMPF(pf[ks2][3], l1);
        }

#pragma unroll
        for (int ks2 = 0; ks2 < 4; ks2++) {
            uint32_t vf[16];
#pragma unroll
            for (int ntp = 0; ntp < 4; ntp++) {
                uint32_t a = vs_b + ((ks2 * 16 + vRow) * SSTR + ntp * 16 + vCol) * 2;
                LDSM4T(vf[4*ntp], vf[4*ntp+1], vf[4*ntp+2], vf[4*ntp+3], a);
            }
#pragma unroll
            for (int ntp = 0; ntp < 4; ntp++) {
                MMA16816(o[2*ntp],   pf[ks2], vf[4*ntp],   vf[4*ntp+1]);
                MMA16816(o[2*ntp+1], pf[ks2], vf[4*ntp+2], vf[4*ntp+3]);
            }
        }
    }

    // single end-of-kernel row-sum reduction (4 lanes share a row)
    l0 += __shfl_xor_sync(0xffffffffu, l0, 1);
    l0 += __shfl_xor_sync(0xffffffffu, l0, 2);
    l1 += __shfl_xor_sync(0xffffffffu, l1, 1);
    l1 += __shfl_xor_sync(0xffffffffu, l1, 2);

    float inv0 = 1.f / l0, inv1 = 1.f / l1;
    int b_ = bh / Hc, h_ = bh % Hc;
    int qrow = q0 + warp * 16 + (lane >> 2);
    __nv_bfloat16* outp = g_attnh + ((size_t)(b_ * Sc + qrow)) * DMc + h_ * HDc;
#pragma unroll
    for (int nt = 0; nt < 8; nt++) {
        int col = nt * 8 + 2 * (lane & 3);
        *(__nv_bfloat162*)(outp + col) =
            __floats2bfloat162_rn(o[nt][0] * inv0, o[nt][1] * inv0);
        *(__nv_bfloat162*)(outp + 8 * DMc + col) =
            __floats2bfloat162_rn(o[nt][2] * inv1, o[nt][3] * inv1);
    }
}

// ---------------------------------------------------------------------------
// LayerNorm over last dim (768), one block per row.
// ---------------------------------------------------------------------------
__global__ __launch_bounds__(256) void ln_kernel(const float* __restrict__ g,
                                                 const float* __restrict__ bb,
                                                 float* __restrict__ out) {
    int row = blockIdx.x;
    const float* yp = g_y + (size_t)row * DMc;
    int tid = threadIdx.x;
    float v0 = yp[tid], v1 = yp[tid + 256], v2 = yp[tid + 512];
    float s = v0 + v1 + v2;

    __shared__ float red[8];
    __shared__ float bc;
#pragma unroll
    for (int o_ = 16; o_ > 0; o_ >>= 1) s += __shfl_xor_sync(0xffffffffu, s, o_);
    if ((tid & 31) == 0) red[tid >> 5] = s;
    __syncthreads();
    if (tid == 0) {
        float tsum = 0.f;
#pragma unroll
        for (int i = 0; i < 8; i++) tsum += red[i];
        bc = tsum;
    }
    __syncthreads();
    float mu = bc * (1.0f / (float)DMc);
    float d0 = v0 - mu, d1 = v1 - mu, d2 = v2 - mu;
    float sq = d0 * d0 + d1 * d1 + d2 * d2;
    __syncthreads();
#pragma unroll
    for (int o_ = 16; o_ > 0; o_ >>= 1) sq += __shfl_xor_sync(0xffffffffu, sq, o_);
    if ((tid & 31) == 0) red[tid >> 5] = sq;
    __syncthreads();
    if (tid == 0) {
        float tsum = 0.f;
#pragma unroll
        for (int i = 0; i < 8; i++) tsum += red[i];
        bc = tsum;
    }
    __syncthreads();
    float var = bc * (1.0f / (float)DMc);
    float inv = rsqrtf(var + 1e-12f);
    size_t base = (size_t)row * DMc;
    out[base + tid]       = d0 * inv * g[tid]       + bb[tid];
    out[base + tid + 256] = d1 * inv * g[tid + 256] + bb[tid + 256];
    out[base + tid + 512] = d2 * inv * g[tid + 512] + bb[tid + 512];
}

// ---------------------------------------------------------------------------
extern "C" void kernel_launch(void* const* d_in, const int* in_sizes, int n_in,
                              void* d_out, int out_size) {
    const float* hidden = (const float*)d_in[0];
    const float* cosp   = (const float*)d_in[1];
    const float* sinp   = (const float*)d_in[2];
    const float* Wq     = (const float*)d_in[3];
    const float* bq     = (const float*)d_in[4];
    const float* Wk     = (const float*)d_in[5];
    const float* bk     = (const float*)d_in[6];
    const float* Wv     = (const float*)d_in[7];
    const float* bv     = (const float*)d_in[8];
    const float* Wo     = (const float*)d_in[9];
    const float* ln_g   = (const float*)d_in[10];
    const float* ln_b   = (const float*)d_in[11];
    float* out = (float*)d_out;

    __nv_bfloat16* xh; cudaGetSymbolAddress((void**)&xh, g_xh);
    __nv_bfloat16* wh; cudaGetSymbolAddress((void**)&wh, g_wh);
    __nv_bfloat16* ah; cudaGetSymbolAddress((void**)&ah, g_attnh);

    cudaFuncSetAttribute(gemm_tc<0>, cudaFuncAttributeMaxDynamicSharedMemorySize, GEMM_SMEM);
    cudaFuncSetAttribute(gemm_tc<1>, cudaFuncAttributeMaxDynamicSharedMemorySize, GEMM_SMEM);

    int nH4 = (Bc * Sc * DMc) / 4;
    dim3 cgrid((nH4 + 255) / 256, 5);
    f2b_all_kernel<<<cgrid, 256>>>(hidden, Wq, Wk, Wv, Wo);

    dim3 qkvgrid(DMc / 128, (Bc * Sc) / 128, 3);   // (6, 64, 3)
    gemm_tc<0><<<qkvgrid, 256, GEMM_SMEM>>>(xh, wh, bq, bk, bv, nullptr, cosp, sinp);

    dim3 agrid(Sc / 64, BHc);                      // (64, 24)
    flash_mma_kernel<<<agrid, 128>>>();

    dim3 ogrid(DMc / 128, (Bc * Sc) / 128, 1);
    gemm_tc<1><<<ogrid, 256, GEMM_SMEM>>>(ah, wh, nullptr, nullptr, nullptr, hidden, cosp, sinp);

    ln_kernel<<<Bc * Sc, 256>>>(ln_g, ln_b, out);
}

// round 14
// speedup vs baseline: 1.0617x; 1.0617x over previous
#include <cuda_runtime.h>
#include <cuda_bf16.h>
#include <math.h>
#include <stdint.h>

#define Bc 2
#define Sc 4096
#define DMc 768
#define Hc 12
#define HDc 64
#define BHc (Bc*Hc)

#define LOG2E 1.4426950408889634f

// Scratch (allocation-free rule: __device__ globals)
__device__ __nv_bfloat16 g_xh[(size_t)Bc*Sc*DMc];     // bf16 hidden
__device__ __nv_bfloat16 g_wh[4][(size_t)DMc*DMc];    // bf16 Wq,Wk,Wv,Wo
__device__ __nv_bfloat16 g_qh[(size_t)BHc*Sc*HDc];    // bf16 q (RoPE'd, * log2e/64)
__device__ __nv_bfloat16 g_kh[(size_t)BHc*Sc*HDc];    // bf16 k (RoPE'd)
__device__ __nv_bfloat16 g_vh[(size_t)BHc*Sc*HDc];    // bf16 v
__device__ __nv_bfloat16 g_attnh[(size_t)Bc*Sc*DMc];  // bf16 attn out
__device__ float g_y[(size_t)Bc*Sc*DMc];              // fp32 pre-LN

// ---------------------------------------------------------------------------
// fp32 -> bf16 converts: grid.y = 0 -> hidden, 1..4 -> Wq..Wo
// ---------------------------------------------------------------------------
__global__ __launch_bounds__(256) void f2b_all_kernel(const float* __restrict__ hidden,
                                                      const float* __restrict__ Wq,
                                                      const float* __restrict__ Wk,
                                                      const float* __restrict__ Wv,
                                                      const float* __restrict__ Wo) {
    int which = blockIdx.y;
    const float* src;
    __nv_bfloat16* dst;
    int n4;
    if (which == 0) { src = hidden; dst = g_xh; n4 = (Bc * Sc * DMc) / 4; }
    else {
        src = (which == 1) ? Wq : (which == 2) ? Wk : (which == 3) ? Wv : Wo;
        dst = g_wh[which - 1];
        n4 = (DMc * DMc) / 4;
    }
    int i = blockIdx.x * blockDim.x + threadIdx.x;
    if (i >= n4) return;
    float4 v = *(const float4*)(src + (size_t)i * 4);
    __nv_bfloat162 a = __floats2bfloat162_rn(v.x, v.y);
    __nv_bfloat162 b = __floats2bfloat162_rn(v.z, v.w);
    *(__nv_bfloat162*)(dst + (size_t)i * 4 + 0) = a;
    *(__nv_bfloat162*)(dst + (size_t)i * 4 + 2) = b;
}

// ---------------------------------------------------------------------------
// helpers
// ---------------------------------------------------------------------------
__device__ __forceinline__ uint32_t pack_bf16(float lo, float hi) {
    __nv_bfloat162 h = __floats2bfloat162_rn(lo, hi);
    return *reinterpret_cast<uint32_t*>(&h);
}
__device__ __forceinline__ void cpa16(uint32_t s, const void* g) {
    asm volatile("cp.async.cg.shared.global [%0], [%1], 16;" :: "r"(s), "l"(g));
}
#define CP_COMMIT() asm volatile("cp.async.commit_group;")
#define CP_WAIT0()  asm volatile("cp.async.wait_group 0;")

#define LDSM4(r0,r1,r2,r3,addr) \
    asm volatile("ldmatrix.sync.aligned.m8n8.x4.shared.b16 {%0,%1,%2,%3},[%4];" \
                 : "=r"(r0),"=r"(r1),"=r"(r2),"=r"(r3) : "r"(addr))
#define LDSM4T(r0,r1,r2,r3,addr) \
    asm volatile("ldmatrix.sync.aligned.m8n8.x4.trans.shared.b16 {%0,%1,%2,%3},[%4];" \
                 : "=r"(r0),"=r"(r1),"=r"(r2),"=r"(r3) : "r"(addr))
#define MMA16816(c, a, b0, b1) \
    asm volatile("mma.sync.aligned.m16n8k16.row.col.f32.bf16.bf16.f32 " \
                 "{%0,%1,%2,%3},{%4,%5,%6,%7},{%8,%9},{%0,%1,%2,%3};" \
                 : "+f"((c)[0]),"+f"((c)[1]),"+f"((c)[2]),"+f"((c)[3]) \
                 : "r"((a)[0]),"r"((a)[1]),"r"((a)[2]),"r"((a)[3]),"r"(b0),"r"(b1))

// packed bf16x2 exp2 on the MUFU pipe: 2 results per instruction
#define EX2_BF16X2(dst, src) \
    asm("ex2.approx.ftz.bf16x2 %0, %1;" : "=r"(dst) : "r"(src))

// ---------------------------------------------------------------------------
// Tensor-core GEMM: 256 threads / 8 warps, tile 128M x 128N, K-chunks of 64,
// double-buffered cp.async (R13 config, 44.4us). Warp layout: warpM=warp>>1,
// warpN=warp&1.
// MODE 0 (grid.z = sel): 0 -> RoPE * log2e/64 -> g_qh ; 1 -> RoPE -> g_kh ;
//                        2 -> +bias -> g_vh.  [b,h,s,d] bf16.
// MODE 1: g_y = acc + resid  (X = g_attnh)
// ---------------------------------------------------------------------------
#define GSTR 72
#define GEMM_SMEM ((2*128*GSTR + 2*128*GSTR) * 2)   // 73728 bytes

template <int MODE>
__global__ __launch_bounds__(256, 2) void gemm_tc(const __nv_bfloat16* __restrict__ X,
                                                  const __nv_bfloat16* __restrict__ Wbase,
                                                  const float* __restrict__ bq,
                                                  const float* __restrict__ bk,
                                                  const float* __restrict__ bv,
                                                  const float* __restrict__ resid,
                                                  const float* __restrict__ cosp,
                                                  const float* __restrict__ sinp) {
    extern __shared__ __align__(16) char smem_raw[];
    __nv_bfloat16* Xs = (__nv_bfloat16*)smem_raw;        // 2 x 128 x GSTR
    __nv_bfloat16* Ws = Xs + 2 * 128 * GSTR;             // 2 x 128 x GSTR

    const int tid  = threadIdx.x;
    const int warp = tid >> 5;
    const int lane = tid & 31;
    const int warpM = warp >> 1;        // 0..3
    const int warpN = warp & 1;         // 0..1
    const int rowBase = blockIdx.y * 128;
    const int colBase = blockIdx.x * 128;
    const int sel = (MODE == 0) ? blockIdx.z : 3;

    const __nv_bfloat16* W = Wbase + (size_t)sel * DMc * DMc;
    const float* bias = (MODE == 0) ? ((sel == 0) ? bq : (sel == 1) ? bk : bv) : nullptr;

    const uint32_t xs_b = (uint32_t)__cvta_generic_to_shared(Xs);
    const uint32_t ws_b = (uint32_t)__cvta_generic_to_shared(Ws);

    auto prefetch = [&](int kb, int buf) {
#pragma unroll
        for (int u = 0; u < 4; u++) {                    // X: 1024 16B-chunks
            int i = u * 256 + tid;
            int r = i >> 3, c = i & 7;
            cpa16(xs_b + ((buf * 128 + r) * GSTR + c * 8) * 2,
                  X + (size_t)(rowBase + r) * DMc + kb + c * 8);
        }
#pragma unroll
        for (int u = 0; u < 4; u++) {                    // W: 1024 16B-chunks
            int i = u * 256 + tid;
            int r = i >> 3, c = i & 7;
            cpa16(ws_b + ((buf * 128 + r) * GSTR + c * 8) * 2,
                  W + (size_t)(colBase + r) * DMc + kb + c * 8);
        }
    };

    float acc[2][8][4];
#pragma unroll
    for (int mt = 0; mt < 2; mt++)
#pragma unroll
        for (int nt = 0; nt < 8; nt++)
#pragma unroll
            for (int i = 0; i < 4; i++) acc[mt][nt][i] = 0.f;

    const int q8 = lane >> 3;
    const int bRow = ((q8 >> 1) * 8) + (lane & 7);
    const int bCol = (q8 & 1) * 8;
    const int aRow = lane & 15;
    const int aCol = (lane >> 4) * 8;

    prefetch(0, 0);
    CP_COMMIT();

    const int NCHUNK = DMc / 64;   // 12
    for (int kc = 0; kc < NCHUNK; kc++) {
        CP_WAIT0();
        __syncthreads();
        if (kc + 1 < NCHUNK) {
            prefetch((kc + 1) * 64, (kc + 1) & 1);
            CP_COMMIT();
        }
        int buf = kc & 1;
#pragma unroll
        for (int ks = 0; ks < 4; ks++) {
            uint32_t af[2][4];
#pragma unroll
            for (int mt = 0; mt < 2; mt++) {
                uint32_t a = xs_b + ((buf * 128 + warpM * 32 + mt * 16 + aRow) * GSTR + ks * 16 + aCol) * 2;
                LDSM4(af[mt][0], af[mt][1], af[mt][2], af[mt][3], a);
            }
            uint32_t bf[16];
#pragma unroll
            for (int ntp = 0; ntp < 4; ntp++) {
                uint32_t a = ws_b + ((buf * 128 + warpN * 64 + ntp * 16 + bRow) * GSTR + ks * 16 + bCol) * 2;
                LDSM4(bf[4*ntp], bf[4*ntp+1], bf[4*ntp+2], bf[4*ntp+3], a);
            }
#pragma unroll
            for (int mt = 0; mt < 2; mt++)
#pragma unroll
                for (int ntp = 0; ntp < 4; ntp++) {
                    MMA16816(acc[mt][2*ntp],   af[mt], bf[4*ntp],   bf[4*ntp+1]);
                    MMA16816(acc[mt][2*ntp+1], af[mt], bf[4*ntp+2], bf[4*ntp+3]);
                }
        }
    }

    // ---- epilogue ----
    if (MODE == 1) {
#pragma unroll
        for (int mt = 0; mt < 2; mt++) {
            int r0 = rowBase + warpM * 32 + mt * 16 + (lane >> 2);
#pragma unroll
            for (int nt = 0; nt < 8; nt++) {
                int col = colBase + warpN * 64 + nt * 8 + 2 * (lane & 3);
                size_t o0 = (size_t)r0 * DMc + col;
                size_t o1 = (size_t)(r0 + 8) * DMc + col;
                float2 w0 = make_float2(acc[mt][nt][0] + resid[o0],
                                        acc[mt][nt][1] + resid[o0 + 1]);
                float2 w1 = make_float2(acc[mt][nt][2] + resid[o1],
                                        acc[mt][nt][3] + resid[o1 + 1]);
                *(float2*)(g_y + o0) = w0;
                *(float2*)(g_y + o1) = w1;
            }
        }
        return;
    }

    __nv_bfloat16* dst = (sel == 0) ? g_qh : (sel == 1) ? g_kh : g_vh;
    const int headCol = colBase + warpN * 64;   // this warp's head base column
    const int h_ = headCol >> 6;
    const float scale = (sel == 0) ? (LOG2E / (float)HDc) : 1.0f;

#pragma unroll
    for (int mt = 0; mt < 2; mt++) {
        int r0 = rowBase + warpM * 32 + mt * 16 + (lane >> 2);
        int r1 = r0 + 8;
        int b0_ = r0 >> 12, s0_ = r0 & (Sc - 1);
        int b1_ = r1 >> 12, s1_ = r1 & (Sc - 1);
        size_t base0 = (((size_t)(b0_ * Hc + h_)) * Sc + s0_) * HDc;
        size_t base1 = (((size_t)(b1_ * Hc + h_)) * Sc + s1_) * HDc;

        if (sel == 2) {
#pragma unroll
            for (int nt = 0; nt < 8; nt++) {
                int d = nt * 8 + 2 * (lane & 3);
                float b_lo = bias[headCol + d], b_hi = bias[headCol + d + 1];
                *(__nv_bfloat162*)(dst + base0 + d) =
                    __floats2bfloat162_rn(acc[mt][nt][0] + b_lo, acc[mt][nt][1] + b_hi);
                *(__nv_bfloat162*)(dst + base1 + d) =
                    __floats2bfloat162_rn(acc[mt][nt][2] + b_lo, acc[mt][nt][3] + b_hi);
            }
        } else {
            // RoPE: pair (d, d+32) lives in (nt, nt+4)
#pragma unroll
            for (int nt = 0; nt < 4; nt++) {
                int d = nt * 8 + 2 * (lane & 3);
                float bl = bias[headCol + d],      bh = bias[headCol + d + 1];
                float bL = bias[headCol + d + 32], bH = bias[headCol + d + 33];
                float2 c0 = *(const float2*)(cosp + (size_t)s0_ * HDc + d);
                float2 sn0 = *(const float2*)(sinp + (size_t)s0_ * HDc + d);
                float2 c1 = *(const float2*)(cosp + (size_t)s1_ * HDc + d);
                float2 sn1 = *(const float2*)(sinp + (size_t)s1_ * HDc + d);
                {
                    float xa0 = acc[mt][nt][0] + bl,  xa1 = acc[mt][nt][1] + bh;
                    float xb0 = acc[mt][nt+4][0] + bL, xb1 = acc[mt][nt+4][1] + bH;
                    float lo0 = (xa0 * c0.x - xb0 * sn0.x) * scale;
                    float lo1 = (xa1 * c0.y - xb1 * sn0.y) * scale;
                    float hi0 = (xb0 * c0.x + xa0 * sn0.x) * scale;
                    float hi1 = (xb1 * c0.y + xa1 * sn0.y) * scale;
                    *(__nv_bfloat162*)(dst + base0 + d)      = __floats2bfloat162_rn(lo0, lo1);
                    *(__nv_bfloat162*)(dst + base0 + d + 32) = __floats2bfloat162_rn(hi0, hi1);
                }
                {
                    float xa0 = acc[mt][nt][2] + bl,  xa1 = acc[mt][nt][3] + bh;
                    float xb0 = acc[mt][nt+4][2] + bL, xb1 = acc[mt][nt+4][3] + bH;
                    float lo0 = (xa0 * c1.x - xb0 * sn1.x) * scale;
                    float lo1 = (xa1 * c1.y - xb1 * sn1.y) * scale;
                    float hi0 = (xb0 * c1.x + xa0 * sn1.x) * scale;
                    float hi1 = (xb1 * c1.y + xa1 * sn1.y) * scale;
                    *(__nv_bfloat162*)(dst + base1 + d)      = __floats2bfloat162_rn(lo0, lo1);
                    *(__nv_bfloat162*)(dst + base1 + d + 32) = __floats2bfloat162_rn(hi0, hi1);
                }
            }
        }
    }
}

// ---------------------------------------------------------------------------
// Flash attention — R11 proven body (bf16x2 exp2 + ones-MMA row sums, the
// minimal-issue softmax) + __launch_bounds__(128, 4): smem is 45KB (allows 5
// CTAs/SM), so capping regs at 128 lifts occupancy from 3 to 4 CTAs/SM.
// ---------------------------------------------------------------------------
#define SSTR 72
#define ONES_BF16X2 0x3F803F80u

__global__ __launch_bounds__(128, 4) void flash_mma_kernel() {
    __shared__ __align__(16) __nv_bfloat16 Qs[64 * SSTR];
    __shared__ __align__(16) __nv_bfloat16 Ks[2][64 * SSTR];
    __shared__ __align__(16) __nv_bfloat16 Vs[2][64 * SSTR];

    const int tid  = threadIdx.x;
    const int warp = tid >> 5;
    const int lane = tid & 31;
    const int bh   = blockIdx.y;
    const int q0   = blockIdx.x * 64;

    const __nv_bfloat16* qg = g_qh + ((size_t)bh * Sc + q0) * HDc;
    const __nv_bfloat16* kg = g_kh + (size_t)bh * Sc * HDc;
    const __nv_bfloat16* vg = g_vh + (size_t)bh * Sc * HDc;

    const uint32_t qs_b = (uint32_t)__cvta_generic_to_shared(Qs);
    const uint32_t ks0 = (uint32_t)__cvta_generic_to_shared(Ks[0]);
    const uint32_t vs0 = (uint32_t)__cvta_generic_to_shared(Vs[0]);
    const uint32_t kvstep = (uint32_t)(64 * SSTR * 2);

    auto prefkv = [&](int j0, int buf) {
        uint32_t kb = ks0 + buf * kvstep;
        uint32_t vb = vs0 + buf * kvstep;
#pragma unroll
        for (int u = 0; u < 4; u++) {
            int i = u * 128 + tid;
            int r = i >> 3, c = i & 7;
            cpa16(kb + (r * SSTR + c * 8) * 2, kg + (size_t)(j0 + r) * HDc + c * 8);
            cpa16(vb + (r * SSTR + c * 8) * 2, vg + (size_t)(j0 + r) * HDc + c * 8);
        }
    };

#pragma unroll
    for (int u = 0; u < 4; u++) {
        int i = u * 128 + tid;
        int r = i >> 3, c = i & 7;
        *(uint4*)&Qs[r * SSTR + c * 8] = *(const uint4*)(qg + (size_t)r * HDc + c * 8);
    }
    prefkv(0, 0);
    CP_COMMIT();
    __syncthreads();

    uint32_t qf[4][4];
    {
        int row = (lane & 15);
        int colo = (lane >= 16) ? 8 : 0;
#pragma unroll
        for (int ks = 0; ks < 4; ks++) {
            uint32_t a = qs_b + ((warp * 16 + row) * SSTR + ks * 16 + colo) * 2;
            LDSM4(qf[ks][0], qf[ks][1], qf[ks][2], qf[ks][3], a);
        }
    }

    const int q8 = lane >> 3;
    const int kRow = ((q8 >> 1) * 8) + (lane & 7);
    const int kCol = (q8 & 1) * 8;
    const int vRow = ((q8 & 1) * 8) + (lane & 7);
    const int vCol = (q8 >> 1) * 8;

    float o[8][4];
#pragma unroll
    for (int nt = 0; nt < 8; nt++)
#pragma unroll
        for (int i = 0; i < 4; i++) o[nt][i] = 0.f;
    float lacc[4] = {0.f, 0.f, 0.f, 0.f};   // row sums via ones-MMA

    const int NT = Sc / 64;   // 64 tiles
    for (int jt = 0; jt < NT; jt++) {
        CP_WAIT0();
        __syncthreads();
        if (jt + 1 < NT) {
            prefkv((jt + 1) * 64, (jt + 1) & 1);
            CP_COMMIT();
        }
        int buf = jt & 1;
        uint32_t ks_b = ks0 + buf * kvstep;
        uint32_t vs_b = vs0 + buf * kvstep;

        float s[8][4];
#pragma unroll
        for (int nt = 0; nt < 8; nt++)
#pragma unroll
            for (int i = 0; i < 4; i++) s[nt][i] = 0.f;

#pragma unroll
        for (int ks = 0; ks < 4; ks++) {
            uint32_t kf[16];
#pragma unroll
            for (int ntp = 0; ntp < 4; ntp++) {
                uint32_t a = ks_b + ((ntp * 16 + kRow) * SSTR + ks * 16 + kCol) * 2;
                LDSM4(kf[4*ntp], kf[4*ntp+1], kf[4*ntp+2], kf[4*ntp+3], a);
            }
#pragma unroll
            for (int ntp = 0; ntp < 4; ntp++) {
                MMA16816(s[2*ntp],   qf[ks], kf[4*ntp],   kf[4*ntp+1]);
                MMA16816(s[2*ntp+1], qf[ks], kf[4*ntp+2], kf[4*ntp+3]);
            }
        }

        // unnormalized softmax: pack scores to bf16x2, exp2 in bf16x2 (2-wide
        // MUFU), row sums accumulated on the tensor core via B = ones
        // (cheapest in issue slots — flash is total-issue-bound).
        uint32_t pf[4][4];
#pragma unroll
        for (int ks2 = 0; ks2 < 4; ks2++) {
            uint32_t t0 = pack_bf16(s[2*ks2][0],   s[2*ks2][1]);
            uint32_t t1 = pack_bf16(s[2*ks2][2],   s[2*ks2][3]);
            uint32_t t2 = pack_bf16(s[2*ks2+1][0], s[2*ks2+1][1]);
            uint32_t t3 = pack_bf16(s[2*ks2+1][2], s[2*ks2+1][3]);
            EX2_BF16X2(pf[ks2][0], t0);
            EX2_BF16X2(pf[ks2][1], t1);
            EX2_BF16X2(pf[ks2][2], t2);
            EX2_BF16X2(pf[ks2][3], t3);
            MMA16816(lacc, pf[ks2], ONES_BF16X2, ONES_BF16X2);
        }

#pragma unroll
        for (int ks2 = 0; ks2 < 4; ks2++) {
            uint32_t vf[16];
#pragma unroll
            for (int ntp = 0; ntp < 4; ntp++) {
                uint32_t a = vs_b + ((ks2 * 16 + vRow) * SSTR + ntp * 16 + vCol) * 2;
                LDSM4T(vf[4*ntp], vf[4*ntp+1], vf[4*ntp+2], vf[4*ntp+3], a);
            }
#pragma unroll
            for (int ntp = 0; ntp < 4; ntp++) {
                MMA16816(o[2*ntp],   pf[ks2], vf[4*ntp],   vf[4*ntp+1]);
                MMA16816(o[2*ntp+1], pf[ks2], vf[4*ntp+2], vf[4*ntp+3]);
            }
        }
    }

    // lacc[0]/lacc[2] hold the complete row sums (n-replicated) — no shuffles.
    float inv0 = 1.f / lacc[0], inv1 = 1.f / lacc[2];
    int b_ = bh / Hc, h_ = bh % Hc;
    int qrow = q0 + warp * 16 + (lane >> 2);
    __nv_bfloat16* outp = g_attnh + ((size_t)(b_ * Sc + qrow)) * DMc + h_ * HDc;
#pragma unroll
    for (int nt = 0; nt < 8; nt++) {
        int col = nt * 8 + 2 * (lane & 3);
        *(__nv_bfloat162*)(outp + col) =
            __floats2bfloat162_rn(o[nt][0] * inv0, o[nt][1] * inv0);
        *(__nv_bfloat162*)(outp + 8 * DMc + col) =
            __floats2bfloat162_rn(o[nt][2] * inv1, o[nt][3] * inv1);
    }
}

// ---------------------------------------------------------------------------
// LayerNorm over last dim (768), one block per row.
// ---------------------------------------------------------------------------
__global__ __launch_bounds__(256) void ln_kernel(const float* __restrict__ g,
                                                 const float* __restrict__ bb,
                                                 float* __restrict__ out) {
    int row = blockIdx.x;
    const float* yp = g_y + (size_t)row * DMc;
    int tid = threadIdx.x;
    float v0 = yp[tid], v1 = yp[tid + 256], v2 = yp[tid + 512];
    float s = v0 + v1 + v2;

    __shared__ float red[8];
    __shared__ float bc;
#pragma unroll
    for (int o_ = 16; o_ > 0; o_ >>= 1) s += __shfl_xor_sync(0xffffffffu, s, o_);
    if ((tid & 31) == 0) red[tid >> 5] = s;
    __syncthreads();
    if (tid == 0) {
        float tsum = 0.f;
#pragma unroll
        for (int i = 0; i < 8; i++) tsum += red[i];
        bc = tsum;
    }
    __syncthreads();
    float mu = bc * (1.0f / (float)DMc);
    float d0 = v0 - mu, d1 = v1 - mu, d2 = v2 - mu;
    float sq = d0 * d0 + d1 * d1 + d2 * d2;
    __syncthreads();
#pragma unroll
    for (int o_ = 16; o_ > 0; o_ >>= 1) sq += __shfl_xor_sync(0xffffffffu, sq, o_);
    if ((tid & 31) == 0) red[tid >> 5] = sq;
    __syncthreads();
    if (tid == 0) {
        float tsum = 0.f;
#pragma unroll
        for (int i = 0; i < 8; i++) tsum += red[i];
        bc = tsum;
    }
    __syncthreads();
    float var = bc * (1.0f / (float)DMc);
    float inv = rsqrtf(var + 1e-12f);
    size_t base = (size_t)row * DMc;
    out[base + tid]       = d0 * inv * g[tid]       + bb[tid];
    out[base + tid + 256] = d1 * inv * g[tid + 256] + bb[tid + 256];
    out[base + tid + 512] = d2 * inv * g[tid + 512] + bb[tid + 512];
}

// ---------------------------------------------------------------------------
extern "C" void kernel_launch(void* const* d_in, const int* in_sizes, int n_in,
                              void* d_out, int out_size) {
    const float* hidden = (const float*)d_in[0];
    const float* cosp   = (const float*)d_in[1];
    const float* sinp   = (const float*)d_in[2];
    const float* Wq     = (const float*)d_in[3];
    const float* bq     = (const float*)d_in[4];
    const float* Wk     = (const float*)d_in[5];
    const float* bk     = (const float*)d_in[6];
    const float* Wv     = (const float*)d_in[7];
    const float* bv     = (const float*)d_in[8];
    const float* Wo     = (const float*)d_in[9];
    const float* ln_g   = (const float*)d_in[10];
    const float* ln_b   = (const float*)d_in[11];
    float* out = (float*)d_out;

    __nv_bfloat16* xh; cudaGetSymbolAddress((void**)&xh, g_xh);
    __nv_bfloat16* wh; cudaGetSymbolAddress((void**)&wh, g_wh);
    __nv_bfloat16* ah; cudaGetSymbolAddress((void**)&ah, g_attnh);

    cudaFuncSetAttribute(gemm_tc<0>, cudaFuncAttributeMaxDynamicSharedMemorySize, GEMM_SMEM);
    cudaFuncSetAttribute(gemm_tc<1>, cudaFuncAttributeMaxDynamicSharedMemorySize, GEMM_SMEM);

    int nH4 = (Bc * Sc * DMc) / 4;
    dim3 cgrid((nH4 + 255) / 256, 5);
    f2b_all_kernel<<<cgrid, 256>>>(hidden, Wq, Wk, Wv, Wo);

    dim3 qkvgrid(DMc / 128, (Bc * Sc) / 128, 3);   // (6, 64, 3)
    gemm_tc<0><<<qkvgrid, 256, GEMM_SMEM>>>(xh, wh, bq, bk, bv, nullptr, cosp, sinp);

    dim3 agrid(Sc / 64, BHc);                      // (64, 24)
    flash_mma_kernel<<<agrid, 128>>>();

    dim3 ogrid(DMc / 128, (Bc * Sc) / 128, 1);
    gemm_tc<1><<<ogrid, 256, GEMM_SMEM>>>(ah, wh, nullptr, nullptr, nullptr, hidden, cosp, sinp);

    ln_kernel<<<Bc * Sc, 256>>>(ln_g, ln_b, out);
}

// round 16
// speedup vs baseline: 1.0648x; 1.0029x over previous
#include <cuda_runtime.h>
#include <cuda_bf16.h>
#include <math.h>
#include <stdint.h>

#define Bc 2
#define Sc 4096
#define DMc 768
#define Hc 12
#define HDc 64
#define BHc (Bc*Hc)

#define LOG2E 1.4426950408889634f

// Scratch (allocation-free rule: __device__ globals)
__device__ __nv_bfloat16 g_xh[(size_t)Bc*Sc*DMc];     // bf16 hidden
__device__ __nv_bfloat16 g_wh[4][(size_t)DMc*DMc];    // bf16 Wq,Wk,Wv,Wo
__device__ __nv_bfloat16 g_qh[(size_t)BHc*Sc*HDc];    // bf16 q (RoPE'd, * log2e/64)
__device__ __nv_bfloat16 g_kh[(size_t)BHc*Sc*HDc];    // bf16 k (RoPE'd)
__device__ __nv_bfloat16 g_vh[(size_t)BHc*Sc*HDc];    // bf16 v
__device__ __nv_bfloat16 g_attnh[(size_t)Bc*Sc*DMc];  // bf16 attn out
__device__ float g_y[(size_t)Bc*Sc*DMc];              // fp32 pre-LN

// ---------------------------------------------------------------------------
// fp32 -> bf16 converts: grid.y = 0 -> hidden, 1..4 -> Wq..Wo
// ---------------------------------------------------------------------------
__global__ __launch_bounds__(256) void f2b_all_kernel(const float* __restrict__ hidden,
                                                      const float* __restrict__ Wq,
                                                      const float* __restrict__ Wk,
                                                      const float* __restrict__ Wv,
                                                      const float* __restrict__ Wo) {
    int which = blockIdx.y;
    const float* src;
    __nv_bfloat16* dst;
    int n4;
    if (which == 0) { src = hidden; dst = g_xh; n4 = (Bc * Sc * DMc) / 4; }
    else {
        src = (which == 1) ? Wq : (which == 2) ? Wk : (which == 3) ? Wv : Wo;
        dst = g_wh[which - 1];
        n4 = (DMc * DMc) / 4;
    }
    int i = blockIdx.x * blockDim.x + threadIdx.x;
    if (i >= n4) return;
    float4 v = *(const float4*)(src + (size_t)i * 4);
    __nv_bfloat162 a = __floats2bfloat162_rn(v.x, v.y);
    __nv_bfloat162 b = __floats2bfloat162_rn(v.z, v.w);
    *(__nv_bfloat162*)(dst + (size_t)i * 4 + 0) = a;
    *(__nv_bfloat162*)(dst + (size_t)i * 4 + 2) = b;
}

// ---------------------------------------------------------------------------
// helpers
// ---------------------------------------------------------------------------
__device__ __forceinline__ uint32_t pack_bf16(float lo, float hi) {
    __nv_bfloat162 h = __floats2bfloat162_rn(lo, hi);
    return *reinterpret_cast<uint32_t*>(&h);
}
__device__ __forceinline__ void cpa16(uint32_t s, const void* g) {
    asm volatile("cp.async.cg.shared.global [%0], [%1], 16;" :: "r"(s), "l"(g));
}
#define CP_COMMIT() asm volatile("cp.async.commit_group;")
#define CP_WAIT0()  asm volatile("cp.async.wait_group 0;")

#define LDSM4(r0,r1,r2,r3,addr) \
    asm volatile("ldmatrix.sync.aligned.m8n8.x4.shared.b16 {%0,%1,%2,%3},[%4];" \
                 : "=r"(r0),"=r"(r1),"=r"(r2),"=r"(r3) : "r"(addr))
#define LDSM4T(r0,r1,r2,r3,addr) \
    asm volatile("ldmatrix.sync.aligned.m8n8.x4.trans.shared.b16 {%0,%1,%2,%3},[%4];" \
                 : "=r"(r0),"=r"(r1),"=r"(r2),"=r"(r3) : "r"(addr))
#define MMA16816(c, a, b0, b1) \
    asm volatile("mma.sync.aligned.m16n8k16.row.col.f32.bf16.bf16.f32 " \
                 "{%0,%1,%2,%3},{%4,%5,%6,%7},{%8,%9},{%0,%1,%2,%3};" \
                 : "+f"((c)[0]),"+f"((c)[1]),"+f"((c)[2]),"+f"((c)[3]) \
                 : "r"((a)[0]),"r"((a)[1]),"r"((a)[2]),"r"((a)[3]),"r"(b0),"r"(b1))

// packed bf16x2 exp2 on the MUFU pipe: 2 results per instruction
#define EX2_BF16X2(dst, src) \
    asm("ex2.approx.ftz.bf16x2 %0, %1;" : "=r"(dst) : "r"(src))

// ---------------------------------------------------------------------------
// Tensor-core GEMM: 128 threads / 4 warps, tile 128M x 64N, K-chunks of 64,
// double-buffered cp.async (R8 proven body) + __launch_bounds__(128,4) and
// max smem carveout so 4 CTAs/SM fit (regs 4x16K=64K, smem 4x55.3=221KB<=228).
// MODE 0 (grid.z = sel): 0 -> RoPE * log2e/64 -> g_qh ; 1 -> RoPE -> g_kh ;
//                        2 -> +bias -> g_vh.  [b,h,s,d] bf16.
// MODE 1: g_y = acc + resid  (X = g_attnh)
// ---------------------------------------------------------------------------
#define GSTR 72
#define GEMM_SMEM ((2*128*GSTR + 2*64*GSTR) * 2)   // 55296 bytes

template <int MODE>
__global__ __launch_bounds__(128, 4) void gemm_tc(const __nv_bfloat16* __restrict__ X,
                                                  const __nv_bfloat16* __restrict__ Wbase,
                                                  const float* __restrict__ bq,
                                                  const float* __restrict__ bk,
                                                  const float* __restrict__ bv,
                                                  const float* __restrict__ resid,
                                                  const float* __restrict__ cosp,
                                                  const float* __restrict__ sinp) {
    extern __shared__ __align__(16) char smem_raw[];
    __nv_bfloat16* Xs = (__nv_bfloat16*)smem_raw;        // 2 x 128 x GSTR
    __nv_bfloat16* Ws = Xs + 2 * 128 * GSTR;             // 2 x 64 x GSTR

    const int tid  = threadIdx.x;
    const int warp = tid >> 5;
    const int lane = tid & 31;
    const int rowBase = blockIdx.y * 128;
    const int colBase = blockIdx.x * 64;
    const int sel = (MODE == 0) ? blockIdx.z : 3;

    const __nv_bfloat16* W = Wbase + (size_t)sel * DMc * DMc;
    const float* bias = (MODE == 0) ? ((sel == 0) ? bq : (sel == 1) ? bk : bv) : nullptr;

    const uint32_t xs_b = (uint32_t)__cvta_generic_to_shared(Xs);
    const uint32_t ws_b = (uint32_t)__cvta_generic_to_shared(Ws);

    auto prefetch = [&](int kb, int buf) {
#pragma unroll
        for (int u = 0; u < 8; u++) {                    // X: 1024 16B-chunks
            int i = u * 128 + tid;
            int r = i >> 3, c = i & 7;
            cpa16(xs_b + ((buf * 128 + r) * GSTR + c * 8) * 2,
                  X + (size_t)(rowBase + r) * DMc + kb + c * 8);
        }
#pragma unroll
        for (int u = 0; u < 4; u++) {                    // W: 512 16B-chunks
            int i = u * 128 + tid;
            int r = i >> 3, c = i & 7;
            cpa16(ws_b + ((buf * 64 + r) * GSTR + c * 8) * 2,
                  W + (size_t)(colBase + r) * DMc + kb + c * 8);
        }
    };

    float acc[2][8][4];
#pragma unroll
    for (int mt = 0; mt < 2; mt++)
#pragma unroll
        for (int nt = 0; nt < 8; nt++)
#pragma unroll
            for (int i = 0; i < 4; i++) acc[mt][nt][i] = 0.f;

    const int q8 = lane >> 3;
    const int bRow = ((q8 >> 1) * 8) + (lane & 7);
    const int bCol = (q8 & 1) * 8;
    const int aRow = lane & 15;
    const int aCol = (lane >> 4) * 8;

    prefetch(0, 0);
    CP_COMMIT();

    const int NCHUNK = DMc / 64;   // 12
    for (int kc = 0; kc < NCHUNK; kc++) {
        CP_WAIT0();
        __syncthreads();
        if (kc + 1 < NCHUNK) {
            prefetch((kc + 1) * 64, (kc + 1) & 1);
            CP_COMMIT();
        }
        int buf = kc & 1;
#pragma unroll
        for (int ks = 0; ks < 4; ks++) {
            uint32_t af[2][4];
#pragma unroll
            for (int mt = 0; mt < 2; mt++) {
                uint32_t a = xs_b + ((buf * 128 + warp * 32 + mt * 16 + aRow) * GSTR + ks * 16 + aCol) * 2;
                LDSM4(af[mt][0], af[mt][1], af[mt][2], af[mt][3], a);
            }
            uint32_t bf[16];
#pragma unroll
            for (int ntp = 0; ntp < 4; ntp++) {
                uint32_t a = ws_b + ((buf * 64 + ntp * 16 + bRow) * GSTR + ks * 16 + bCol) * 2;
                LDSM4(bf[4*ntp], bf[4*ntp+1], bf[4*ntp+2], bf[4*ntp+3], a);
            }
#pragma unroll
            for (int mt = 0; mt < 2; mt++)
#pragma unroll
                for (int ntp = 0; ntp < 4; ntp++) {
                    MMA16816(acc[mt][2*ntp],   af[mt], bf[4*ntp],   bf[4*ntp+1]);
                    MMA16816(acc[mt][2*ntp+1], af[mt], bf[4*ntp+2], bf[4*ntp+3]);
                }
        }
    }

    // ---- epilogue ----
    if (MODE == 1) {
#pragma unroll
        for (int mt = 0; mt < 2; mt++) {
            int r0 = rowBase + warp * 32 + mt * 16 + (lane >> 2);
#pragma unroll
            for (int nt = 0; nt < 8; nt++) {
                int col = colBase + nt * 8 + 2 * (lane & 3);
                size_t o0 = (size_t)r0 * DMc + col;
                size_t o1 = (size_t)(r0 + 8) * DMc + col;
                float2 w0 = make_float2(acc[mt][nt][0] + resid[o0],
                                        acc[mt][nt][1] + resid[o0 + 1]);
                float2 w1 = make_float2(acc[mt][nt][2] + resid[o1],
                                        acc[mt][nt][3] + resid[o1 + 1]);
                *(float2*)(g_y + o0) = w0;
                *(float2*)(g_y + o1) = w1;
            }
        }
        return;
    }

    __nv_bfloat16* dst = (sel == 0) ? g_qh : (sel == 1) ? g_kh : g_vh;
    const int h_ = colBase >> 6;
    const float scale = (sel == 0) ? (LOG2E / (float)HDc) : 1.0f;

#pragma unroll
    for (int mt = 0; mt < 2; mt++) {
        int r0 = rowBase + warp * 32 + mt * 16 + (lane >> 2);
        int r1 = r0 + 8;
        int b0_ = r0 >> 12, s0_ = r0 & (Sc - 1);
        int b1_ = r1 >> 12, s1_ = r1 & (Sc - 1);
        size_t base0 = (((size_t)(b0_ * Hc + h_)) * Sc + s0_) * HDc;
        size_t base1 = (((size_t)(b1_ * Hc + h_)) * Sc + s1_) * HDc;

        if (sel == 2) {
#pragma unroll
            for (int nt = 0; nt < 8; nt++) {
                int d = nt * 8 + 2 * (lane & 3);
                float b_lo = bias[colBase + d], b_hi = bias[colBase + d + 1];
                *(__nv_bfloat162*)(dst + base0 + d) =
                    __floats2bfloat162_rn(acc[mt][nt][0] + b_lo, acc[mt][nt][1] + b_hi);
                *(__nv_bfloat162*)(dst + base1 + d) =
                    __floats2bfloat162_rn(acc[mt][nt][2] + b_lo, acc[mt][nt][3] + b_hi);
            }
        } else {
            // RoPE: pair (d, d+32) lives in (nt, nt+4)
#pragma unroll
            for (int nt = 0; nt < 4; nt++) {
                int d = nt * 8 + 2 * (lane & 3);
                float bl = bias[colBase + d],      bh = bias[colBase + d + 1];
                float bL = bias[colBase + d + 32], bH = bias[colBase + d + 33];
                float2 c0 = *(const float2*)(cosp + (size_t)s0_ * HDc + d);
                float2 sn0 = *(const float2*)(sinp + (size_t)s0_ * HDc + d);
                float2 c1 = *(const float2*)(cosp + (size_t)s1_ * HDc + d);
                float2 sn1 = *(const float2*)(sinp + (size_t)s1_ * HDc + d);
                {
                    float xa0 = acc[mt][nt][0] + bl,  xa1 = acc[mt][nt][1] + bh;
                    float xb0 = acc[mt][nt+4][0] + bL, xb1 = acc[mt][nt+4][1] + bH;
                    float lo0 = (xa0 * c0.x - xb0 * sn0.x) * scale;
                    float lo1 = (xa1 * c0.y - xb1 * sn0.y) * scale;
                    float hi0 = (xb0 * c0.x + xa0 * sn0.x) * scale;
                    float hi1 = (xb1 * c0.y + xa1 * sn0.y) * scale;
                    *(__nv_bfloat162*)(dst + base0 + d)      = __floats2bfloat162_rn(lo0, lo1);
                    *(__nv_bfloat162*)(dst + base0 + d + 32) = __floats2bfloat162_rn(hi0, hi1);
                }
                {
                    float xa0 = acc[mt][nt][2] + bl,  xa1 = acc[mt][nt][3] + bh;
                    float xb0 = acc[mt][nt+4][2] + bL, xb1 = acc[mt][nt+4][3] + bH;
                    float lo0 = (xa0 * c1.x - xb0 * sn1.x) * scale;
                    float lo1 = (xa1 * c1.y - xb1 * sn1.y) * scale;
                    float hi0 = (xb0 * c1.x + xa0 * sn1.x) * scale;
                    float hi1 = (xb1 * c1.y + xa1 * sn1.y) * scale;
                    *(__nv_bfloat162*)(dst + base1 + d)      = __floats2bfloat162_rn(lo0, lo1);
                    *(__nv_bfloat162*)(dst + base1 + d + 32) = __floats2bfloat162_rn(hi0, hi1);
                }
            }
        }
    }
}

// ---------------------------------------------------------------------------
// Flash attention — R14 proven (128 threads / 4 warps, 64 q rows, double-
// buffered K/V cp.async, bf16x2 exp2 + ones-MMA row sums, launch_bounds(128,4)).
// ---------------------------------------------------------------------------
#define SSTR 72
#define ONES_BF16X2 0x3F803F80u

__global__ __launch_bounds__(128, 4) void flash_mma_kernel() {
    __shared__ __align__(16) __nv_bfloat16 Qs[64 * SSTR];
    __shared__ __align__(16) __nv_bfloat16 Ks[2][64 * SSTR];
    __shared__ __align__(16) __nv_bfloat16 Vs[2][64 * SSTR];

    const int tid  = threadIdx.x;
    const int warp = tid >> 5;
    const int lane = tid & 31;
    const int bh   = blockIdx.y;
    const int q0   = blockIdx.x * 64;

    const __nv_bfloat16* qg = g_qh + ((size_t)bh * Sc + q0) * HDc;
    const __nv_bfloat16* kg = g_kh + (size_t)bh * Sc * HDc;
    const __nv_bfloat16* vg = g_vh + (size_t)bh * Sc * HDc;

    const uint32_t qs_b = (uint32_t)__cvta_generic_to_shared(Qs);
    const uint32_t ks0 = (uint32_t)__cvta_generic_to_shared(Ks[0]);
    const uint32_t vs0 = (uint32_t)__cvta_generic_to_shared(Vs[0]);
    const uint32_t kvstep = (uint32_t)(64 * SSTR * 2);

    auto prefkv = [&](int j0, int buf) {
        uint32_t kb = ks0 + buf * kvstep;
        uint32_t vb = vs0 + buf * kvstep;
#pragma unroll
        for (int u = 0; u < 4; u++) {
            int i = u * 128 + tid;
            int r = i >> 3, c = i & 7;
            cpa16(kb + (r * SSTR + c * 8) * 2, kg + (size_t)(j0 + r) * HDc + c * 8);
            cpa16(vb + (r * SSTR + c * 8) * 2, vg + (size_t)(j0 + r) * HDc + c * 8);
        }
    };

#pragma unroll
    for (int u = 0; u < 4; u++) {
        int i = u * 128 + tid;
        int r = i >> 3, c = i & 7;
        *(uint4*)&Qs[r * SSTR + c * 8] = *(const uint4*)(qg + (size_t)r * HDc + c * 8);
    }
    prefkv(0, 0);
    CP_COMMIT();
    __syncthreads();

    uint32_t qf[4][4];
    {
        int row = (lane & 15);
        int colo = (lane >= 16) ? 8 : 0;
#pragma unroll
        for (int ks = 0; ks < 4; ks++) {
            uint32_t a = qs_b + ((warp * 16 + row) * SSTR + ks * 16 + colo) * 2;
            LDSM4(qf[ks][0], qf[ks][1], qf[ks][2], qf[ks][3], a);
        }
    }

    const int q8 = lane >> 3;
    const int kRow = ((q8 >> 1) * 8) + (lane & 7);
    const int kCol = (q8 & 1) * 8;
    const int vRow = ((q8 & 1) * 8) + (lane & 7);
    const int vCol = (q8 >> 1) * 8;

    float o[8][4];
#pragma unroll
    for (int nt = 0; nt < 8; nt++)
#pragma unroll
        for (int i = 0; i < 4; i++) o[nt][i] = 0.f;
    float lacc[4] = {0.f, 0.f, 0.f, 0.f};

    const int NT = Sc / 64;
    for (int jt = 0; jt < NT; jt++) {
        CP_WAIT0();
        __syncthreads();
        if (jt + 1 < NT) {
            prefkv((jt + 1) * 64, (jt + 1) & 1);
            CP_COMMIT();
        }
        int buf = jt & 1;
        uint32_t ks_b = ks0 + buf * kvstep;
        uint32_t vs_b = vs0 + buf * kvstep;

        float s[8][4];
#pragma unroll
        for (int nt = 0; nt < 8; nt++)
#pragma unroll
            for (int i = 0; i < 4; i++) s[nt][i] = 0.f;

#pragma unroll
        for (int ks = 0; ks < 4; ks++) {
            uint32_t kf[16];
#pragma unroll
            for (int ntp = 0; ntp < 4; ntp++) {
                uint32_t a = ks_b + ((ntp * 16 + kRow) * SSTR + ks * 16 + kCol) * 2;
                LDSM4(kf[4*ntp], kf[4*ntp+1], kf[4*ntp+2], kf[4*ntp+3], a);
            }
#pragma unroll
            for (int ntp = 0; ntp < 4; ntp++) {
                MMA16816(s[2*ntp],   qf[ks], kf[4*ntp],   kf[4*ntp+1]);
                MMA16816(s[2*ntp+1], qf[ks], kf[4*ntp+2], kf[4*ntp+3]);
            }
        }

        uint32_t pf[4][4];
#pragma unroll
        for (int ks2 = 0; ks2 < 4; ks2++) {
            uint32_t t0 = pack_bf16(s[2*ks2][0],   s[2*ks2][1]);
            uint32_t t1 = pack_bf16(s[2*ks2][2],   s[2*ks2][3]);
            uint32_t t2 = pack_bf16(s[2*ks2+1][0], s[2*ks2+1][1]);
            uint32_t t3 = pack_bf16(s[2*ks2+1][2], s[2*ks2+1][3]);
            EX2_BF16X2(pf[ks2][0], t0);
            EX2_BF16X2(pf[ks2][1], t1);
            EX2_BF16X2(pf[ks2][2], t2);
            EX2_BF16X2(pf[ks2][3], t3);
            MMA16816(lacc, pf[ks2], ONES_BF16X2, ONES_BF16X2);
        }

#pragma unroll
        for (int ks2 = 0; ks2 < 4; ks2++) {
            uint32_t vf[16];
#pragma unroll
            for (int ntp = 0; ntp < 4; ntp++) {
                uint32_t a = vs_b + ((ks2 * 16 + vRow) * SSTR + ntp * 16 + vCol) * 2;
                LDSM4T(vf[4*ntp], vf[4*ntp+1], vf[4*ntp+2], vf[4*ntp+3], a);
            }
#pragma unroll
            for (int ntp = 0; ntp < 4; ntp++) {
                MMA16816(o[2*ntp],   pf[ks2], vf[4*ntp],   vf[4*ntp+1]);
                MMA16816(o[2*ntp+1], pf[ks2], vf[4*ntp+2], vf[4*ntp+3]);
            }
        }
    }

    float inv0 = 1.f / lacc[0], inv1 = 1.f / lacc[2];
    int b_ = bh / Hc, h_ = bh % Hc;
    int qrow = q0 + warp * 16 + (lane >> 2);
    __nv_bfloat16* outp = g_attnh + ((size_t)(b_ * Sc + qrow)) * DMc + h_ * HDc;
#pragma unroll
    for (int nt = 0; nt < 8; nt++) {
        int col = nt * 8 + 2 * (lane & 3);
        *(__nv_bfloat162*)(outp + col) =
            __floats2bfloat162_rn(o[nt][0] * inv0, o[nt][1] * inv0);
        *(__nv_bfloat162*)(outp + 8 * DMc + col) =
            __floats2bfloat162_rn(o[nt][2] * inv1, o[nt][3] * inv1);
    }
}

// ---------------------------------------------------------------------------
// LayerNorm over last dim (768), one block per row.
// ---------------------------------------------------------------------------
__global__ __launch_bounds__(256) void ln_kernel(const float* __restrict__ g,
                                                 const float* __restrict__ bb,
                                                 float* __restrict__ out) {
    int row = blockIdx.x;
    const float* yp = g_y + (size_t)row * DMc;
    int tid = threadIdx.x;
    float v0 = yp[tid], v1 = yp[tid + 256], v2 = yp[tid + 512];
    float s = v0 + v1 + v2;

    __shared__ float red[8];
    __shared__ float bc;
#pragma unroll
    for (int o_ = 16; o_ > 0; o_ >>= 1) s += __shfl_xor_sync(0xffffffffu, s, o_);
    if ((tid & 31) == 0) red[tid >> 5] = s;
    __syncthreads();
    if (tid == 0) {
        float tsum = 0.f;
#pragma unroll
        for (int i = 0; i < 8; i++) tsum += red[i];
        bc = tsum;
    }
    __syncthreads();
    float mu = bc * (1.0f / (float)DMc);
    float d0 = v0 - mu, d1 = v1 - mu, d2 = v2 - mu;
    float sq = d0 * d0 + d1 * d1 + d2 * d2;
    __syncthreads();
#pragma unroll
    for (int o_ = 16; o_ > 0; o_ >>= 1) sq += __shfl_xor_sync(0xffffffffu, sq, o_);
    if ((tid & 31) == 0) red[tid >> 5] = sq;
    __syncthreads();
    if (tid == 0) {
        float tsum = 0.f;
#pragma unroll
        for (int i = 0; i < 8; i++) tsum += red[i];
        bc = tsum;
    }
    __syncthreads();
    float var = bc * (1.0f / (float)DMc);
    float inv = rsqrtf(var + 1e-12f);
    size_t base = (size_t)row * DMc;
    out[base + tid]       = d0 * inv * g[tid]       + bb[tid];
    out[base + tid + 256] = d1 * inv * g[tid + 256] + bb[tid + 256];
    out[base + tid + 512] = d2 * inv * g[tid + 512] + bb[tid + 512];
}

// ---------------------------------------------------------------------------
extern "C" void kernel_launch(void* const* d_in, const int* in_sizes, int n_in,
                              void* d_out, int out_size) {
    const float* hidden = (const float*)d_in[0];
    const float* cosp   = (const float*)d_in[1];
    const float* sinp   = (const float*)d_in[2];
    const float* Wq     = (const float*)d_in[3];
    const float* bq     = (const float*)d_in[4];
    const float* Wk     = (const float*)d_in[5];
    const float* bk     = (const float*)d_in[6];
    const float* Wv     = (const float*)d_in[7];
    const float* bv     = (const float*)d_in[8];
    const float* Wo     = (const float*)d_in[9];
    const float* ln_g   = (const float*)d_in[10];
    const float* ln_b   = (const float*)d_in[11];
    float* out = (float*)d_out;

    __nv_bfloat16* xh; cudaGetSymbolAddress((void**)&xh, g_xh);
    __nv_bfloat16* wh; cudaGetSymbolAddress((void**)&wh, g_wh);
    __nv_bfloat16* ah; cudaGetSymbolAddress((void**)&ah, g_attnh);

    cudaFuncSetAttribute(gemm_tc<0>, cudaFuncAttributeMaxDynamicSharedMemorySize, GEMM_SMEM);
    cudaFuncSetAttribute(gemm_tc<1>, cudaFuncAttributeMaxDynamicSharedMemorySize, GEMM_SMEM);
    // request max smem carveout so 4 CTAs (221 KB) can be resident
    cudaFuncSetAttribute(gemm_tc<0>, cudaFuncAttributePreferredSharedMemoryCarveout, 100);
    cudaFuncSetAttribute(gemm_tc<1>, cudaFuncAttributePreferredSharedMemoryCarveout, 100);

    int nH4 = (Bc * Sc * DMc) / 4;
    dim3 cgrid((nH4 + 255) / 256, 5);
    f2b_all_kernel<<<cgrid, 256>>>(hidden, Wq, Wk, Wv, Wo);

    dim3 qkvgrid(DMc / 64, (Bc * Sc) / 128, 3);   // (12, 64, 3)
    gemm_tc<0><<<qkvgrid, 128, GEMM_SMEM>>>(xh, wh, bq, bk, bv, nullptr, cosp, sinp);

    dim3 agrid(Sc / 64, BHc);                     // (64, 24)
    flash_mma_kernel<<<agrid, 128>>>();

    dim3 ogrid(DMc / 64, (Bc * Sc) / 128, 1);
    gemm_tc<1><<<ogrid, 128, GEMM_SMEM>>>(ah, wh, nullptr, nullptr, nullptr, hidden, cosp, sinp);

    ln_kernel<<<Bc * Sc, 256>>>(ln_g, ln_b, out);
}